// round 6
// baseline (speedup 1.0000x reference)
#include <cuda_runtime.h>
#include <cstdint>

#define BB      4
#define CINC    64
#define COUTC   64
#define KNB     16
#define NN      32768
#define PTS     128       // points per CTA (= GEMM M)
#define VROW    260       // row stride (words), ≡4 mod 32: conflict-free frags
#define THREADS 1024

// ---- scratch (no allocations allowed) ----
__device__ float  g_featT[(size_t)BB * NN * CINC];   // [b][n][c] fp32
__device__ float4 g_posT [(size_t)BB * NN];          // [b][n] xyz_

__device__ __forceinline__ uint32_t f32_to_tf32(float x) {
    uint32_t r;
    asm("cvt.rna.tf32.f32 %0, %1;" : "=r"(r) : "f"(x));
    return r;
}
__device__ __forceinline__ uint64_t pack2(float x, float y) {
    uint64_t r;
    asm("mov.b64 %0, {%1, %2};" : "=l"(r) : "f"(x), "f"(y));
    return r;
}
__device__ __forceinline__ void unpack2(float& x, float& y, uint64_t v) {
    asm("mov.b64 {%0, %1}, %2;" : "=f"(x), "=f"(y) : "l"(v));
}
__device__ __forceinline__ void fma2(uint64_t& d, uint64_t a, uint64_t b) {
    asm("fma.rn.f32x2 %0, %1, %2, %0;" : "+l"(d) : "l"(a), "l"(b));
}
__device__ __forceinline__ void add2(uint64_t& d, uint64_t a) {
    asm("add.rn.f32x2 %0, %0, %1;" : "+l"(d) : "l"(a));
}

// m16n8k8 tf32 MMA (sm_80+ PTX, HMMA on sm_103a)
__device__ __forceinline__ void mma_tf32(float d[4],
    uint32_t a0, uint32_t a1, uint32_t a2, uint32_t a3,
    uint32_t b0, uint32_t b1)
{
    asm volatile(
        "mma.sync.aligned.m16n8k8.row.col.f32.tf32.tf32.f32 "
        "{%0,%1,%2,%3}, {%4,%5,%6,%7}, {%8,%9}, {%0,%1,%2,%3};"
        : "+f"(d[0]), "+f"(d[1]), "+f"(d[2]), "+f"(d[3])
        : "r"(a0), "r"(a1), "r"(a2), "r"(a3), "r"(b0), "r"(b1));
}

// smem layout (32-bit words)
static constexpr int SW_W4   = 0;                        // [64 o][VROW k]
static constexpr int SW_VS   = 64 * VROW;                // [128 p][VROW cc]
static constexpr int SW_DP   = SW_VS + PTS * VROW;       // [4 g][8 kk][32 p] float4
static constexpr int SW_BIAS = SW_DP + 4 * 8 * 32 * 4;   // [64]
static constexpr int SMEM_WORDS = SW_BIAS + 64;
static constexpr int SMEM_BYTES = SMEM_WORDS * 4;        // 216,320 B

// ---------------------------------------------------------------------------
// Kernel 1a: transpose features [B][CIN][N] -> [B][N][CIN] (fp32, 64x64 tiles)
// ---------------------------------------------------------------------------
__global__ void __launch_bounds__(256) transpose_feat(const float4* __restrict__ f4) {
    __shared__ float tile[64][65];
    const int b  = blockIdx.y;
    const int n0 = blockIdx.x * 64;
    const int tx = threadIdx.x & 15;
    const int ty = threadIdx.x >> 4;
    const float4* src = f4 + (size_t)b * CINC * (NN / 4) + (n0 >> 2);
    #pragma unroll
    for (int cc = ty; cc < 64; cc += 16) {
        float4 v = __ldg(&src[(size_t)cc * (NN / 4) + tx]);
        tile[4 * tx + 0][cc] = v.x;
        tile[4 * tx + 1][cc] = v.y;
        tile[4 * tx + 2][cc] = v.z;
        tile[4 * tx + 3][cc] = v.w;
    }
    __syncthreads();
    float4* dst = (float4*)(g_featT + ((size_t)b * NN + n0) * CINC);
    #pragma unroll
    for (int rr = ty; rr < 64; rr += 16) {
        float4 v = make_float4(tile[rr][4 * tx], tile[rr][4 * tx + 1],
                               tile[rr][4 * tx + 2], tile[rr][4 * tx + 3]);
        dst[(size_t)rr * 16 + tx] = v;
    }
}

// ---------------------------------------------------------------------------
// Kernel 1b: positions -> float4 rows
// ---------------------------------------------------------------------------
__global__ void prep_pos(const float* __restrict__ pos) {
    const int t = blockIdx.x * blockDim.x + threadIdx.x;   // over B*N
    const int b = t / NN;
    const int n = t - b * NN;
    const float* p = pos + (size_t)b * 3 * NN;
    g_posT[t] = make_float4(p[n], p[NN + n], p[2 * NN + n], 0.f);
}

// ---------------------------------------------------------------------------
// Main: 4 subgroups x 8 warps; per group: dp-prep -> gather -> V -> GEMM,
// synced by named barriers only (groups overlap memory vs tensor phases).
// ---------------------------------------------------------------------------
__global__ void __launch_bounds__(THREADS, 1) flexconv_main(
    const float* __restrict__ wt,    // [3][CIN][COUT]
    const float* __restrict__ wb,    // [CIN][COUT]
    const float* __restrict__ bias,  // [COUT]
    const int*   __restrict__ nbin,  // [B][K][N]
    float* __restrict__ out)         // [B][COUT][N]
{
    extern __shared__ uint32_t smw[];
    uint32_t* W4s = smw + SW_W4;     // [o][k] stride VROW
    uint32_t* Vs  = smw + SW_VS;     // [p][cc] stride VROW
    float*    bs  = (float*)(smw + SW_BIAS);

    const int tid = threadIdx.x;
    const int w   = tid >> 5, l = tid & 31;
    const int g   = w >> 3;          // subgroup 0..3
    const int wg  = w & 7;           // warp in group
    const int tg  = tid & 255;       // thread in group
    const int bar = g + 1;           // named barrier id
    const int b   = blockIdx.y;
    const int n0  = blockIdx.x * PTS;

    if (tid < COUTC) bs[tid] = bias[tid];

    // stage W4 -> [o][k] (tf32), gmem-coalesced over o
    #pragma unroll
    for (int it = 0; it < (256 * 64) / THREADS; it++) {
        int t = tid + it * THREADS;
        int k = t >> 6, o = t & 63;
        float v = (k < 192) ? wt[t] : wb[t - 192 * 64];
        W4s[o * VROW + k] = f32_to_tf32(v);
    }
    __syncthreads();   // W4/bias visible to all groups

    // ---------------- phase 1: per-group gather + reduce --------------------
    float4* dpb = (float4*)(smw + SW_DP) + g * 256;       // [kk][p]
    const float2* featT2 = (const float2*)g_featT;
    const float4* posT   = g_posT + (size_t)b * NN;

    uint64_t acc[4][4];               // [point i][d] packed f32x2 (2 channels)
    #pragma unroll
    for (int i = 0; i < 4; i++)
        acc[i][0] = acc[i][1] = acc[i][2] = acc[i][3] = 0ull;

    #pragma unroll
    for (int h = 0; h < 2; h++) {
        // prep: one (p,kk) entry per thread; nb read fully coalesced
        {
            const int p  = tg & 31, kk = tg >> 5;
            const int k  = 8 * h + kk;
            const int n  = n0 + g * 32 + p;
            const int idx = __ldg(&nbin[((size_t)b * KNB + k) * NN + n]);
            const float4 pg = __ldg(&posT[idx]);
            const float4 ps = __ldg(&posT[n]);
            dpb[kk * 32 + p] = make_float4(pg.x - ps.x, pg.y - ps.y, pg.z - ps.z,
                                           __int_as_float((b * NN + idx) << 5));
        }
        asm volatile("bar.sync %0, %1;" :: "r"(bar), "r"(256) : "memory");

        #pragma unroll 1
        for (int i = 0; i < 4; i++) {                     // 4 points per warp
            const int p = wg * 4 + i;
            #pragma unroll
            for (int kk = 0; kk < 8; kk++) {
                float4 q = dpb[kk * 32 + p];
                float2 f = __ldg(&featT2[__float_as_int(q.w) + l]);
                uint64_t fp = pack2(f.x, f.y);
                fma2(acc[i][0], pack2(q.x, q.x), fp);
                fma2(acc[i][1], pack2(q.y, q.y), fp);
                fma2(acc[i][2], pack2(q.z, q.z), fp);
                add2(acc[i][3], fp);
            }
        }
        asm volatile("bar.sync %0, %1;" :: "r"(bar), "r"(256) : "memory");
    }

    // write V rows (tf32), lane l owns channels 2l, 2l+1
    #pragma unroll
    for (int i = 0; i < 4; i++) {
        const int p = g * 32 + wg * 4 + i;
        uint32_t* vrow = Vs + p * VROW;
        #pragma unroll
        for (int d = 0; d < 4; d++) {
            float x, y;
            unpack2(x, y, acc[i][d]);
            vrow[d * 64 + 2 * l]     = f32_to_tf32(x);
            vrow[d * 64 + 2 * l + 1] = f32_to_tf32(y);
        }
    }
    asm volatile("bar.sync %0, %1;" :: "r"(bar), "r"(256) : "memory");

    // ---------------- phase 2: per-group tf32 GEMM 32x64x256 ----------------
    // group's 8 warps: m16 x n16 tiles over its 32 points
    const int mw = 2 * g + (wg & 1);  // global M tile (16 rows)
    const int nq = wg >> 1;           // N quarter (16 cols)
    const int r  = l >> 2, c = l & 3;

    float dacc[2][4];
    #pragma unroll
    for (int t = 0; t < 2; t++)
        dacc[t][0] = dacc[t][1] = dacc[t][2] = dacc[t][3] = 0.f;

    const uint32_t* Va = Vs + (16 * mw + r) * VROW + c;
    const uint32_t* Wr = W4s + (16 * nq + r) * VROW + c;  // [o][k]

    #pragma unroll 8
    for (int k0 = 0; k0 < 256; k0 += 8) {
        uint32_t a0 = Va[k0];
        uint32_t a1 = Va[8 * VROW + k0];
        uint32_t a2 = Va[k0 + 4];
        uint32_t a3 = Va[8 * VROW + k0 + 4];
        #pragma unroll
        for (int t = 0; t < 2; t++) {
            uint32_t b0 = Wr[8 * t * VROW + k0];
            uint32_t b1 = Wr[8 * t * VROW + k0 + 4];
            mma_tf32(dacc[t], a0, a1, a2, a3, b0, b1);
        }
    }

    // ---------------- epilogue: bias + store --------------------------------
    float* op = out + (size_t)b * COUTC * NN + n0 + 16 * mw + r;
    #pragma unroll
    for (int t = 0; t < 2; t++) {
        int o0 = 16 * nq + 8 * t + 2 * c;
        float bv0 = bs[o0], bv1 = bs[o0 + 1];
        op[(size_t)o0 * NN]           = dacc[t][0] + bv0;
        op[(size_t)(o0 + 1) * NN]     = dacc[t][1] + bv1;
        op[(size_t)o0 * NN + 8]       = dacc[t][2] + bv0;
        op[(size_t)(o0 + 1) * NN + 8] = dacc[t][3] + bv1;
    }
}

// ---------------------------------------------------------------------------
extern "C" void kernel_launch(void* const* d_in, const int* in_sizes, int n_in,
                              void* d_out, int out_size) {
    const float* feat = (const float*)d_in[0];   // [B][CIN][N]
    const float* wt   = (const float*)d_in[1];   // [3][CIN][COUT]
    const float* wb   = (const float*)d_in[2];   // [CIN][COUT]
    const float* bias = (const float*)d_in[3];   // [COUT]
    const int*   nb   = (const int*)  d_in[4];   // [B][K][N]
    const float* pos  = (const float*)d_in[5];   // [B][3][N]
    float* out = (float*)d_out;

    transpose_feat<<<dim3(NN / 64, BB), 256>>>((const float4*)feat);
    prep_pos<<<(BB * NN) / 256, 256>>>(pos);

    cudaFuncSetAttribute(flexconv_main,
                         cudaFuncAttributeMaxDynamicSharedMemorySize, SMEM_BYTES);
    flexconv_main<<<dim3(NN / PTS, BB), THREADS, SMEM_BYTES>>>(wt, wb, bias, nb, out);
}

// round 7
// speedup vs baseline: 1.2630x; 1.2630x over previous
#include <cuda_runtime.h>
#include <cstdint>

#define BB      4
#define CINC    64
#define COUTC   64
#define KNB     16
#define NN      32768
#define PTS     128       // points per CTA (= GEMM M)
#define VROW    260       // V row stride (words): A-frag LDS conflict-free
#define WSTR    72        // W4 row stride (words): B-frag LDS conflict-free
#define THREADS 1024

// ---- scratch (no allocations allowed) ----
__device__ float  g_featT[(size_t)BB * NN * CINC];   // [b][n][c]
__device__ float4 g_posT [(size_t)BB * NN];          // [b][n] xyz_
__device__ int    g_nbT  [(size_t)BB * NN * KNB];    // [b][n][k]

__device__ __forceinline__ uint32_t f32_to_tf32(float x) {
    uint32_t r;
    asm("cvt.rna.tf32.f32 %0, %1;" : "=r"(r) : "f"(x));
    return r;
}
__device__ __forceinline__ uint64_t pack2(float x, float y) {
    uint64_t r;
    asm("mov.b64 %0, {%1, %2};" : "=l"(r) : "f"(x), "f"(y));
    return r;
}
__device__ __forceinline__ void unpack2(float& x, float& y, uint64_t v) {
    asm("mov.b64 {%0, %1}, %2;" : "=f"(x), "=f"(y) : "l"(v));
}
__device__ __forceinline__ void fma2(uint64_t& d, uint64_t a, uint64_t b) {
    asm("fma.rn.f32x2 %0, %1, %2, %0;" : "+l"(d) : "l"(a), "l"(b));
}
__device__ __forceinline__ void add2(uint64_t& d, uint64_t a) {
    asm("add.rn.f32x2 %0, %0, %1;" : "+l"(d) : "l"(a));
}

// m16n8k8 tf32 MMA (sm_80+ PTX, HMMA on sm_103a)
__device__ __forceinline__ void mma_tf32(float d[4],
    uint32_t a0, uint32_t a1, uint32_t a2, uint32_t a3,
    uint32_t b0, uint32_t b1)
{
    asm volatile(
        "mma.sync.aligned.m16n8k8.row.col.f32.tf32.tf32.f32 "
        "{%0,%1,%2,%3}, {%4,%5,%6,%7}, {%8,%9}, {%0,%1,%2,%3};"
        : "+f"(d[0]), "+f"(d[1]), "+f"(d[2]), "+f"(d[3])
        : "r"(a0), "r"(a1), "r"(a2), "r"(a3), "r"(b0), "r"(b1));
}

// smem layout (32-bit words)
static constexpr int SW_W4   = 0;                       // [256][WSTR]
static constexpr int SW_VS   = 256 * WSTR;              // [PTS][VROW]
static constexpr int SW_BIAS = SW_VS + PTS * VROW;      // [64]
static constexpr int SMEM_WORDS = SW_BIAS + 64;
static constexpr int SMEM_BYTES = SMEM_WORDS * 4;       // ~207.6 KB

// ---------------------------------------------------------------------------
// Kernel 1a: transpose features [B][CIN][N] -> [B][N][CIN], 64x64 float4 tiles
// ---------------------------------------------------------------------------
__global__ void __launch_bounds__(256) transpose_feat(const float4* __restrict__ f4) {
    __shared__ float tile[64][65];
    const int b  = blockIdx.y;
    const int n0 = blockIdx.x * 64;
    const int tx = threadIdx.x & 15;
    const int ty = threadIdx.x >> 4;
    const float4* src = f4 + (size_t)b * CINC * (NN / 4) + (n0 >> 2);
    #pragma unroll
    for (int cc = ty; cc < 64; cc += 16) {
        float4 v = __ldg(&src[(size_t)cc * (NN / 4) + tx]);
        tile[4 * tx + 0][cc] = v.x;
        tile[4 * tx + 1][cc] = v.y;
        tile[4 * tx + 2][cc] = v.z;
        tile[4 * tx + 3][cc] = v.w;
    }
    __syncthreads();
    float4* dst = (float4*)(g_featT + (size_t)b * NN * CINC) + (size_t)n0 * 16;
    #pragma unroll
    for (int rr = ty; rr < 64; rr += 16) {
        float4 v = make_float4(tile[rr][4 * tx], tile[rr][4 * tx + 1],
                               tile[rr][4 * tx + 2], tile[rr][4 * tx + 3]);
        dst[(size_t)rr * 16 + tx] = v;
    }
}

// ---------------------------------------------------------------------------
// Kernel 1b: positions -> float4 rows; neighborhood -> [b][n][k]
// ---------------------------------------------------------------------------
__global__ void prep_pos_nb(const float* __restrict__ pos, const int* __restrict__ nb) {
    const int t = blockIdx.x * blockDim.x + threadIdx.x;   // over B*N
    const int b = t / NN;
    const int n = t - b * NN;
    const float* p = pos + (size_t)b * 3 * NN;
    g_posT[t] = make_float4(p[n], p[NN + n], p[2 * NN + n], 0.f);
    const int* s = nb + (size_t)b * KNB * NN;
    int* d = g_nbT + (size_t)t * KNB;
    #pragma unroll
    for (int k = 0; k < KNB; k++) d[k] = s[(size_t)k * NN + n];
}

// ---------------------------------------------------------------------------
// Main: gather+reduce (f32x2, hoisted center) -> V(tf32, smem) -> tf32 GEMM
//   V[p][cc], cc = d*64 + c : d=0..2 -> S[d][c], d=3 -> fsum[c]
//   W4[cc][o] = [theta(192 rows); wb(64 rows)]
// ---------------------------------------------------------------------------
__global__ void __launch_bounds__(THREADS, 1) flexconv_main(
    const float* __restrict__ wt,    // [3][CIN][COUT]
    const float* __restrict__ wb,    // [CIN][COUT]
    const float* __restrict__ bias,  // [COUT]
    float* __restrict__ out)         // [B][COUT][N]
{
    extern __shared__ uint32_t smw[];
    uint32_t* W4s = smw + SW_W4;
    uint32_t* Vs  = smw + SW_VS;
    float*    bs  = (float*)(smw + SW_BIAS);

    const int tid = threadIdx.x;
    const int w   = tid >> 5, l = tid & 31;
    const int b   = blockIdx.y;
    const int n0  = blockIdx.x * PTS;

    if (tid < COUTC) bs[tid] = bias[tid];

    // stage W4 -> [k][o] with stride WSTR, converted to tf32 (coalesced over o)
    #pragma unroll
    for (int it = 0; it < (256 * 64) / THREADS; it++) {
        int t = tid + it * THREADS;
        int k = t >> 6, o = t & 63;
        float v = (k < 192) ? wt[t] : wb[t - 192 * 64];
        W4s[k * WSTR + o] = f32_to_tf32(v);
    }

    // ---------------- phase 1: gather + neighbor reduction ----------------
    // S_d = sum_k pg_d * f  -  ps_d * sum_k f   (center term hoisted)
    const float2* featT2 = (const float2*)g_featT;        // [(b*N+idx)*32 + l]
    const float4* posT   = g_posT + (size_t)b * NN;

    #pragma unroll 1
    for (int i = 0; i < 4; i++) {                         // 32 warps x 4 points
        const int p = w * 4 + i;
        const int n = n0 + p;
        const int* nbrow = g_nbT + ((size_t)b * NN + n) * KNB;
        int myidx = nbrow[l & 15];
        const float4 ps = __ldg(&posT[n]);
        uint64_t a0 = 0ull, a1 = 0ull, a2 = 0ull, af = 0ull;
        #pragma unroll
        for (int k = 0; k < KNB; k++) {
            int idx = __shfl_sync(0xffffffffu, myidx, k);
            float4 pg = __ldg(&posT[idx]);
            float2 f  = __ldg(&featT2[((size_t)b * NN + idx) * 32 + l]);
            uint64_t fp = pack2(f.x, f.y);
            fma2(a0, pack2(pg.x, pg.x), fp);
            fma2(a1, pack2(pg.y, pg.y), fp);
            fma2(a2, pack2(pg.z, pg.z), fp);
            add2(af, fp);
        }
        // center correction: a_d -= ps_d * af
        fma2(a0, pack2(-ps.x, -ps.x), af);
        fma2(a1, pack2(-ps.y, -ps.y), af);
        fma2(a2, pack2(-ps.z, -ps.z), af);

        uint32_t* vrow = Vs + p * VROW;                   // cc = d*64 + 2l
        float x, y;
        unpack2(x, y, a0);
        vrow[0 * 64 + 2 * l] = f32_to_tf32(x);  vrow[0 * 64 + 2 * l + 1] = f32_to_tf32(y);
        unpack2(x, y, a1);
        vrow[1 * 64 + 2 * l] = f32_to_tf32(x);  vrow[1 * 64 + 2 * l + 1] = f32_to_tf32(y);
        unpack2(x, y, a2);
        vrow[2 * 64 + 2 * l] = f32_to_tf32(x);  vrow[2 * 64 + 2 * l + 1] = f32_to_tf32(y);
        unpack2(x, y, af);
        vrow[3 * 64 + 2 * l] = f32_to_tf32(x);  vrow[3 * 64 + 2 * l + 1] = f32_to_tf32(y);
    }
    __syncthreads();

    // ---------------- phase 2: tf32 tensor GEMM 128x64x256 -----------------
    // 32 warps: warp tile m16 x n16, full K. 2 n8-tiles per warp.
    const int mw = w & 7;            // M tile index (8 tiles x 16 rows)
    const int nq = w >> 3;           // N quarter index (4 x 16 cols)
    const int r  = l >> 2, c = l & 3;

    float acc[2][4];
    #pragma unroll
    for (int t = 0; t < 2; t++)
        acc[t][0] = acc[t][1] = acc[t][2] = acc[t][3] = 0.f;

    const uint32_t* Va = Vs + (16 * mw + r) * VROW + c;   // +0 / +8*VROW rows
    const uint32_t* Wb = W4s + 16 * nq + r;               // [k][o]

    #pragma unroll 8
    for (int k0 = 0; k0 < 256; k0 += 8) {
        uint32_t a0 = Va[k0];
        uint32_t a1 = Va[8 * VROW + k0];
        uint32_t a2 = Va[k0 + 4];
        uint32_t a3 = Va[8 * VROW + k0 + 4];
        const uint32_t* wk0 = Wb + (k0 + c) * WSTR;
        const uint32_t* wk1 = Wb + (k0 + c + 4) * WSTR;
        #pragma unroll
        for (int t = 0; t < 2; t++)
            mma_tf32(acc[t], a0, a1, a2, a3, wk0[8 * t], wk1[8 * t]);
    }

    // ---------------- epilogue: bias + store --------------------------------
    float* op = out + (size_t)b * COUTC * NN + n0 + 16 * mw + r;
    #pragma unroll
    for (int t = 0; t < 2; t++) {
        int o0 = 16 * nq + 8 * t + 2 * c;
        float bv0 = bs[o0], bv1 = bs[o0 + 1];
        op[(size_t)o0 * NN]           = acc[t][0] + bv0;
        op[(size_t)(o0 + 1) * NN]     = acc[t][1] + bv1;
        op[(size_t)o0 * NN + 8]       = acc[t][2] + bv0;
        op[(size_t)(o0 + 1) * NN + 8] = acc[t][3] + bv1;
    }
}

// ---------------------------------------------------------------------------
extern "C" void kernel_launch(void* const* d_in, const int* in_sizes, int n_in,
                              void* d_out, int out_size) {
    const float* feat = (const float*)d_in[0];   // [B][CIN][N]
    const float* wt   = (const float*)d_in[1];   // [3][CIN][COUT]
    const float* wb   = (const float*)d_in[2];   // [CIN][COUT]
    const float* bias = (const float*)d_in[3];   // [COUT]
    const int*   nb   = (const int*)  d_in[4];   // [B][K][N]
    const float* pos  = (const float*)d_in[5];   // [B][3][N]
    float* out = (float*)d_out;

    transpose_feat<<<dim3(NN / 64, BB), 256>>>((const float4*)feat);
    prep_pos_nb<<<(BB * NN) / 256, 256>>>(pos, nb);

    cudaFuncSetAttribute(flexconv_main,
                         cudaFuncAttributeMaxDynamicSharedMemorySize, SMEM_BYTES);
    flexconv_main<<<dim3(NN / PTS, BB), THREADS, SMEM_BYTES>>>(wt, wb, bias, out);
}

// round 8
// speedup vs baseline: 1.3219x; 1.0466x over previous
#include <cuda_runtime.h>
#include <cstdint>

#define BB      4
#define CINC    64
#define COUTC   64
#define KNB     16
#define NN      32768
#define PTS     128       // points per tile (= GEMM M)
#define VROW    260       // V row stride (words): A-frag LDS conflict-free
#define WSTR    72        // W4 row stride (words): B-frag LDS conflict-free
#define THREADS 1024
#define GRIDM   148       // persistent CTAs (1/SM)
#define NTILES  (BB * (NN / PTS))   // 1024

// ---- scratch (no allocations allowed) ----
__device__ float  g_featT[(size_t)BB * NN * CINC];   // [b][n][c]
__device__ float4 g_posT [(size_t)BB * NN];          // [b][n] xyz_
__device__ int    g_nbT  [(size_t)BB * NN * KNB];    // [b][n][k]

__device__ __forceinline__ uint32_t f32_to_tf32(float x) {
    uint32_t r;
    asm("cvt.rna.tf32.f32 %0, %1;" : "=r"(r) : "f"(x));
    return r;
}
__device__ __forceinline__ uint64_t pack2(float x, float y) {
    uint64_t r;
    asm("mov.b64 %0, {%1, %2};" : "=l"(r) : "f"(x), "f"(y));
    return r;
}
__device__ __forceinline__ void unpack2(float& x, float& y, uint64_t v) {
    asm("mov.b64 {%0, %1}, %2;" : "=f"(x), "=f"(y) : "l"(v));
}
__device__ __forceinline__ void fma2(uint64_t& d, uint64_t a, uint64_t b) {
    asm("fma.rn.f32x2 %0, %1, %2, %0;" : "+l"(d) : "l"(a), "l"(b));
}
__device__ __forceinline__ void add2(uint64_t& d, uint64_t a) {
    asm("add.rn.f32x2 %0, %0, %1;" : "+l"(d) : "l"(a));
}

// m16n8k8 tf32 MMA (sm_80+ PTX, HMMA on sm_103a)
__device__ __forceinline__ void mma_tf32(float d[4],
    uint32_t a0, uint32_t a1, uint32_t a2, uint32_t a3,
    uint32_t b0, uint32_t b1)
{
    asm volatile(
        "mma.sync.aligned.m16n8k8.row.col.f32.tf32.tf32.f32 "
        "{%0,%1,%2,%3}, {%4,%5,%6,%7}, {%8,%9}, {%0,%1,%2,%3};"
        : "+f"(d[0]), "+f"(d[1]), "+f"(d[2]), "+f"(d[3])
        : "r"(a0), "r"(a1), "r"(a2), "r"(a3), "r"(b0), "r"(b1));
}

// smem layout (32-bit words)
static constexpr int SW_W4   = 0;                       // [256][WSTR]
static constexpr int SW_VS   = 256 * WSTR;              // [PTS][VROW]
static constexpr int SW_BIAS = SW_VS + PTS * VROW;      // [64]
static constexpr int SMEM_WORDS = SW_BIAS + 64;
static constexpr int SMEM_BYTES = SMEM_WORDS * 4;       // ~207.6 KB

// ---------------------------------------------------------------------------
// Fused prep: blocks [0, 2048) transpose features; blocks [2048, 2560) do
// positions + neighborhood re-layout. Disjoint data -> full overlap.
// ---------------------------------------------------------------------------
__global__ void __launch_bounds__(256) prep_all(
    const float4* __restrict__ f4,   // features as float4
    const float*  __restrict__ pos,  // [B][3][N]
    const int*    __restrict__ nb)   // [B][K][N]
{
    __shared__ float tile[64][65];
    const int bx = blockIdx.x;
    if (bx < (NN / 64) * BB) {
        // ---- transpose features [B][CIN][N] -> [B][N][CIN] ----
        const int b  = bx >> 9;               // NN/64 = 512 blocks per batch
        const int n0 = (bx & 511) * 64;
        const int tx = threadIdx.x & 15;
        const int ty = threadIdx.x >> 4;
        const float4* src = f4 + (size_t)b * CINC * (NN / 4) + (n0 >> 2);
        #pragma unroll
        for (int cc = ty; cc < 64; cc += 16) {
            float4 v = __ldg(&src[(size_t)cc * (NN / 4) + tx]);
            tile[4 * tx + 0][cc] = v.x;
            tile[4 * tx + 1][cc] = v.y;
            tile[4 * tx + 2][cc] = v.z;
            tile[4 * tx + 3][cc] = v.w;
        }
        __syncthreads();
        float4* dst = (float4*)(g_featT + (size_t)b * NN * CINC) + (size_t)n0 * 16;
        #pragma unroll
        for (int rr = ty; rr < 64; rr += 16) {
            float4 v = make_float4(tile[rr][4 * tx], tile[rr][4 * tx + 1],
                                   tile[rr][4 * tx + 2], tile[rr][4 * tx + 3]);
            dst[(size_t)rr * 16 + tx] = v;
        }
    } else {
        // ---- positions -> float4 rows; neighborhood -> [b][n][k] ----
        const int t = (bx - (NN / 64) * BB) * 256 + threadIdx.x;   // over B*N
        const int b = t / NN;
        const int n = t - b * NN;
        const float* p = pos + (size_t)b * 3 * NN;
        g_posT[t] = make_float4(p[n], p[NN + n], p[2 * NN + n], 0.f);
        const int* s = nb + (size_t)b * KNB * NN;
        int* d = g_nbT + (size_t)t * KNB;
        #pragma unroll
        for (int k = 0; k < KNB; k++) d[k] = s[(size_t)k * NN + n];
    }
}

// ---------------------------------------------------------------------------
// Persistent main: W4 staged once; per tile: gather+reduce -> V -> tf32 GEMM.
// ---------------------------------------------------------------------------
__global__ void __launch_bounds__(THREADS, 1) flexconv_main(
    const float* __restrict__ wt,    // [3][CIN][COUT]
    const float* __restrict__ wb,    // [CIN][COUT]
    const float* __restrict__ bias,  // [COUT]
    float* __restrict__ out)         // [B][COUT][N]
{
    extern __shared__ uint32_t smw[];
    uint32_t* W4s = smw + SW_W4;
    uint32_t* Vs  = smw + SW_VS;
    float*    bs  = (float*)(smw + SW_BIAS);

    const int tid = threadIdx.x;
    const int w   = tid >> 5, l = tid & 31;

    if (tid < COUTC) bs[tid] = bias[tid];

    // stage W4 -> [k][o] (tf32) ONCE; visibility guaranteed by loop-top bar
    #pragma unroll
    for (int it = 0; it < (256 * 64) / THREADS; it++) {
        int t = tid + it * THREADS;
        int k = t >> 6, o = t & 63;
        float v = (k < 192) ? wt[t] : wb[t - 192 * 64];
        W4s[k * WSTR + o] = f32_to_tf32(v);
    }

    const float2* featT2 = (const float2*)g_featT;
    // GEMM tile indices (fixed per warp)
    const int mw = w & 7;            // M tile (8 x 16 rows)
    const int nq = w >> 3;           // N quarter (4 x 16 cols)
    const int r  = l >> 2, c = l & 3;

    for (int tile = blockIdx.x; tile < NTILES; tile += GRIDM) {
        const int b  = tile >> 8;                 // NN/PTS = 256 tiles/batch
        const int n0 = (tile & 255) * PTS;
        const float4* posT = g_posT + (size_t)b * NN;

        __syncthreads();   // previous tile's GEMM reads of Vs complete

        // ---------------- gather + neighbor reduction ----------------
        #pragma unroll 1
        for (int i = 0; i < 4; i++) {             // 32 warps x 4 points
            const int p = w * 4 + i;
            const int n = n0 + p;
            const int* nbrow = g_nbT + ((size_t)b * NN + n) * KNB;
            int myidx = nbrow[l & 15];
            const float4 ps = __ldg(&posT[n]);
            uint64_t a0 = 0ull, a1 = 0ull, a2 = 0ull, af = 0ull;
            #pragma unroll
            for (int k = 0; k < KNB; k++) {
                int idx = __shfl_sync(0xffffffffu, myidx, k);
                float4 pg = __ldg(&posT[idx]);
                float2 f  = __ldg(&featT2[((size_t)b * NN + idx) * 32 + l]);
                uint64_t fp = pack2(f.x, f.y);
                fma2(a0, pack2(pg.x, pg.x), fp);
                fma2(a1, pack2(pg.y, pg.y), fp);
                fma2(a2, pack2(pg.z, pg.z), fp);
                add2(af, fp);
            }
            fma2(a0, pack2(-ps.x, -ps.x), af);
            fma2(a1, pack2(-ps.y, -ps.y), af);
            fma2(a2, pack2(-ps.z, -ps.z), af);

            uint32_t* vrow = Vs + p * VROW;       // cc = d*64 + 2l
            float x, y;
            unpack2(x, y, a0);
            vrow[0 * 64 + 2 * l] = f32_to_tf32(x);  vrow[0 * 64 + 2 * l + 1] = f32_to_tf32(y);
            unpack2(x, y, a1);
            vrow[1 * 64 + 2 * l] = f32_to_tf32(x);  vrow[1 * 64 + 2 * l + 1] = f32_to_tf32(y);
            unpack2(x, y, a2);
            vrow[2 * 64 + 2 * l] = f32_to_tf32(x);  vrow[2 * 64 + 2 * l + 1] = f32_to_tf32(y);
            unpack2(x, y, af);
            vrow[3 * 64 + 2 * l] = f32_to_tf32(x);  vrow[3 * 64 + 2 * l + 1] = f32_to_tf32(y);
        }
        __syncthreads();

        // ---------------- tf32 tensor GEMM 128x64x256 ----------------
        float acc[2][4];
        #pragma unroll
        for (int t = 0; t < 2; t++)
            acc[t][0] = acc[t][1] = acc[t][2] = acc[t][3] = 0.f;

        const uint32_t* Va = Vs + (16 * mw + r) * VROW + c;
        const uint32_t* Wb = W4s + 16 * nq + r;

        #pragma unroll 8
        for (int k0 = 0; k0 < 256; k0 += 8) {
            uint32_t a0 = Va[k0];
            uint32_t a1 = Va[8 * VROW + k0];
            uint32_t a2 = Va[k0 + 4];
            uint32_t a3 = Va[8 * VROW + k0 + 4];
            const uint32_t* wk0 = Wb + (k0 + c) * WSTR;
            const uint32_t* wk1 = Wb + (k0 + c + 4) * WSTR;
            #pragma unroll
            for (int t = 0; t < 2; t++)
                mma_tf32(acc[t], a0, a1, a2, a3, wk0[8 * t], wk1[8 * t]);
        }

        // ---------------- epilogue: bias + store ----------------
        float* op = out + (size_t)b * COUTC * NN + n0 + 16 * mw + r;
        #pragma unroll
        for (int t = 0; t < 2; t++) {
            int o0 = 16 * nq + 8 * t + 2 * c;
            float bv0 = bs[o0], bv1 = bs[o0 + 1];
            op[(size_t)o0 * NN]           = acc[t][0] + bv0;
            op[(size_t)(o0 + 1) * NN]     = acc[t][1] + bv1;
            op[(size_t)o0 * NN + 8]       = acc[t][2] + bv0;
            op[(size_t)(o0 + 1) * NN + 8] = acc[t][3] + bv1;
        }
    }
}

// ---------------------------------------------------------------------------
extern "C" void kernel_launch(void* const* d_in, const int* in_sizes, int n_in,
                              void* d_out, int out_size) {
    const float* feat = (const float*)d_in[0];   // [B][CIN][N]
    const float* wt   = (const float*)d_in[1];   // [3][CIN][COUT]
    const float* wb   = (const float*)d_in[2];   // [CIN][COUT]
    const float* bias = (const float*)d_in[3];   // [COUT]
    const int*   nb   = (const int*)  d_in[4];   // [B][K][N]
    const float* pos  = (const float*)d_in[5];   // [B][3][N]
    float* out = (float*)d_out;

    const int nprep = (NN / 64) * BB + (BB * NN) / 256;   // 2048 + 512
    prep_all<<<nprep, 256>>>((const float4*)feat, pos, nb);

    cudaFuncSetAttribute(flexconv_main,
                         cudaFuncAttributeMaxDynamicSharedMemorySize, SMEM_BYTES);
    flexconv_main<<<GRIDM, THREADS, SMEM_BYTES>>>(wt, wb, bias, out);
}